// round 12
// baseline (speedup 1.0000x reference)
#include <cuda_runtime.h>
#include <cuda_bf16.h>

typedef unsigned long long ull;
typedef unsigned int u32;

#define NSAMP 4096
#define DIM   256
#define NCLS  6
#define TDIM  128
#define KC    32
#define NCH   (DIM / KC)            // 8
#define OPB   (TDIM * KC * 2)       // 8192 bytes per operand tile
#define STAGEB (4 * OPB)            // 32768 per stage (Ah,Al,Bh,Bl)
#define SMEM_DYN (2 * STAGEB + 1024)

#define NT0   528                    // 32*33/2 triangular tiles
#define NTILE 2080                   // 1024 ST + 528 SS + 528 TT
#define PGRID 304                    // 2 CTAs x 152 SMs, persistent

// ---------------- device scratch ----------------
__device__ __align__(1024) __nv_bfloat16 g_Sh[NSAMP * DIM];
__device__ __align__(1024) __nv_bfloat16 g_Sl[NSAMP * DIM];
__device__ __align__(1024) __nv_bfloat16 g_Th[NSAMP * DIM];
__device__ __align__(1024) __nv_bfloat16 g_Tl[NSAMP * DIM];
__device__ float  g_ss[NSAMP];
__device__ float  g_tt[NSAMP];
__device__ float  g_colpart[256][DIM];   // per-block column partial sums
__device__ float  g_sqpart[256];         // per-block squared-norm partials
__device__ float  g_neg_inv_bw16;
__device__ ull    g_min_row[NSAMP];
__device__ ull    g_min_col[NSAMP];
__device__ double g_ksum[3];
__device__ double g_clfpart[16];
__device__ double g_dispart[16];
__device__ u32    g_done_ctr;
__device__ int    g_label64;

// ---------------- PTX helpers (baseline ISA only) ----------------
__device__ __forceinline__ u32 smem_u32(const void* p) {
    u32 a;
    asm("{ .reg .u64 t; cvta.to.shared.u64 t, %1; cvt.u32.u64 %0, t; }" : "=r"(a) : "l"(p));
    return a;
}
__device__ __forceinline__ void cp16(u32 dst, const void* src) {
    asm volatile("cp.async.cg.shared.global [%0], [%1], 16;" :: "r"(dst), "l"(src));
}
#define CP_COMMIT() asm volatile("cp.async.commit_group;")
#define CP_WAIT(n)  asm volatile("cp.async.wait_group %0;" :: "n"(n))

__device__ __forceinline__ void ldsm4(u32* r, u32 addr) {
    asm volatile("ldmatrix.sync.aligned.m8n8.x4.shared.b16 {%0,%1,%2,%3}, [%4];"
        : "=r"(r[0]), "=r"(r[1]), "=r"(r[2]), "=r"(r[3]) : "r"(addr));
}
__device__ __forceinline__ void hmma(float* d, const u32* a, const u32* b) {
    asm volatile(
        "mma.sync.aligned.m16n8k16.row.col.f32.bf16.bf16.f32 "
        "{%0,%1,%2,%3}, {%4,%5,%6,%7}, {%8,%9}, {%0,%1,%2,%3};"
        : "+f"(d[0]), "+f"(d[1]), "+f"(d[2]), "+f"(d[3])
        : "r"(a[0]), "r"(a[1]), "r"(a[2]), "r"(a[3]), "r"(b[0]), "r"(b[1]));
}

// 64B-row XOR swizzle (SW64): conflict-free for 8-row x 16B ldmatrix reads
__device__ __forceinline__ u32 swz64(u32 row, u32 colbytes) {
    u32 off = row * 64u + colbytes;
    return off ^ ((off >> 3) & 0x30u);
}

// ---------------- tile decode: ST (heavy) first, triangular last ----------------
__device__ __forceinline__ void decode_tile(int idx, int& mode, int& bi, int& bj) {
    if (idx < 1024) {
        mode = 2; bi = idx >> 5; bj = idx & 31;
    } else {
        int q = idx - 1024;
        mode = (q < NT0) ? 0 : 1;
        if (q >= NT0) q -= NT0;
        int b = 0;
        while (q >= 32 - b) { q -= 32 - b; b++; }
        bi = b; bj = b + q;
    }
}
__device__ __forceinline__ void set_srcs(int mode, int bi, int bj, const __nv_bfloat16** s) {
    s[0] = ((mode == 1) ? g_Th : g_Sh) + (size_t)bi * TDIM * DIM;
    s[1] = ((mode == 1) ? g_Tl : g_Sl) + (size_t)bi * TDIM * DIM;
    s[2] = ((mode == 0) ? g_Sh : g_Th) + (size_t)bj * TDIM * DIM;
    s[3] = ((mode == 0) ? g_Sl : g_Tl) + (size_t)bj * TDIM * DIM;
}
__device__ __forceinline__ void prefetch_chunk(const __nv_bfloat16* const* s, int c,
                                               u32 sb, int tid, int ntl) {
    #pragma unroll
    for (int t = 0; t < 4; t++) {
        if (t < ntl) {
            #pragma unroll
            for (int rep = 0; rep < 2; rep++) {
                int ix = rep * 256 + tid;
                int row = ix >> 2, seg = ix & 3;
                cp16(sb + t * OPB + swz64(row, seg * 16),
                     s[t] + (size_t)row * DIM + c * KC + seg * 8);
            }
        }
    }
}

// ---------------- preprocess: split + norms + partial colsums/sqsum + label detect ----------------
__global__ void preprocess(const float* __restrict__ S, const float* __restrict__ T,
                           const int* __restrict__ lab) {
    __shared__ float tile[32][DIM + 1];
    __shared__ float wsum[8];
    int r0 = blockIdx.x * 32;
    bool isS = (r0 < NSAMP);
    int rloc = isS ? r0 : (r0 - NSAMP);
    const float* X = isS ? (S + (size_t)r0 * DIM) : (T + (size_t)rloc * DIM);
    __nv_bfloat16* H = isS ? (g_Sh + (size_t)r0 * DIM) : (g_Th + (size_t)rloc * DIM);
    __nv_bfloat16* L = isS ? (g_Sl + (size_t)r0 * DIM) : (g_Tl + (size_t)rloc * DIM);

    int tid = threadIdx.x;
    if (blockIdx.x == 0) {
        __shared__ int any;
        if (tid == 0) any = 0;
        __syncthreads();
        for (int k = 1 + 2 * tid; k < NSAMP; k += 2 * blockDim.x)
            if (lab[k] != 0) any = 1;
        __syncthreads();
        if (tid == 0) g_label64 = (any == 0) ? 1 : 0;
    }

    for (int i = tid; i < 32 * DIM; i += 256) {
        float v = X[i];
        tile[i >> 8][i & 255] = v;
        __nv_bfloat16 h = __float2bfloat16(v);
        H[i] = h;
        L[i] = __float2bfloat16(v - __bfloat162float(h));
    }
    __syncthreads();

    int wid = tid >> 5, lane = tid & 31;
    float dsum = 0.f;
    #pragma unroll
    for (int q = 0; q < 4; q++) {
        int rr = wid * 4 + q;
        float s = 0.f;
        for (int c = lane; c < DIM; c += 32) { float v = tile[rr][c]; s += v * v; }
        for (int o = 16; o; o >>= 1) s += __shfl_down_sync(0xffffffffu, s, o);
        if (lane == 0) {
            if (isS) g_ss[r0 + rr] = s; else g_tt[rloc + rr] = s;
            dsum += s;
        }
    }
    if (lane == 0) wsum[wid] = dsum;
    __syncthreads();
    if (tid == 0) {
        float t = 0.f;
        #pragma unroll
        for (int k = 0; k < 8; k++) t += wsum[k];
        g_sqpart[blockIdx.x] = t;
    }

    float cs = 0.f;
    #pragma unroll
    for (int rr = 0; rr < 32; rr++) cs += tile[rr][tid];
    g_colpart[blockIdx.x][tid] = cs;
}

// blocks 0..15: cross-entropy partials + min init; block 16: bandwidth + zero accumulators
__global__ void bw_clf_kernel(const float* __restrict__ sclf, const int* __restrict__ lw) {
    int tid = threadIdx.x;
    if (blockIdx.x == 16) {
        float Sc = 0.f;
        #pragma unroll 8
        for (int b = 0; b < 256; b++) Sc += g_colpart[b][tid];
        double p = (double)Sc * (double)Sc;
        float sq = g_sqpart[tid];
        for (int o = 16; o; o >>= 1) {
            p  += __shfl_down_sync(0xffffffffu, p, o);
            sq += __shfl_down_sync(0xffffffffu, sq, o);
        }
        __shared__ double ws[8];
        __shared__ float  qs[8];
        if ((tid & 31) == 0) { ws[tid >> 5] = p; qs[tid >> 5] = sq; }
        __syncthreads();
        if (tid == 0) {
            double ssv = 0.0, sqv = 0.0;
            #pragma unroll
            for (int k = 0; k < 8; k++) { ssv += ws[k]; sqv += (double)qs[k]; }
            double n = 2.0 * NSAMP;
            double sumL2 = 2.0 * n * sqv - 2.0 * ssv;
            double b = sumL2 / (n * n - n) / 4.0;
            g_neg_inv_bw16 = (float)(-1.0 / (b * 16.0));
            g_ksum[0] = 0.0; g_ksum[1] = 0.0; g_ksum[2] = 0.0;
            g_done_ctr = 0u;
        }
        return;
    }
    int i = blockIdx.x * 256 + tid;
    g_min_row[i] = ~0ull;
    g_min_col[i] = ~0ull;

    const float* x = sclf + i * NCLS;
    float m = x[0];
    #pragma unroll
    for (int c = 1; c < NCLS; c++) m = fmaxf(m, x[c]);
    float se = 0.f;
    #pragma unroll
    for (int c = 0; c < NCLS; c++) se += __expf(x[c] - m);
    float lse = m + __logf(se);
    int lab = g_label64 ? lw[2 * i] : lw[i];
    float loss = lse - x[lab];
    for (int o = 16; o; o >>= 1) loss += __shfl_down_sync(0xffffffffu, loss, o);
    __shared__ float cw[8];
    if ((tid & 31) == 0) cw[tid >> 5] = loss;
    __syncthreads();
    if (tid == 0) {
        float t = 0.f;
        #pragma unroll
        for (int k = 0; k < 8; k++) t += cw[k];
        g_clfpart[blockIdx.x] = (double)t;
    }
}

// ---------------- persistent mma.sync pair kernel ----------------
__global__ __launch_bounds__(256, 2) void pair_all() {
    extern __shared__ char dynraw[];
    __shared__ float naS[TDIM], nbS[TDIM];
    __shared__ ull   sRow[TDIM], sCol[TDIM];

    int tid = threadIdx.x, wid = tid >> 5, lane = tid & 31;
    u32 dbase = (smem_u32(dynraw) + 1023u) & ~1023u;
    int mrow0 = (wid & 3) * 32;
    int ncol0 = (wid >> 2) * 64;
    int a_row = lane & 15;
    int a_kb  = (lane >> 4) * 16;
    int b_row = (lane & 7) + ((lane >> 4) ? 8 : 0);
    int b_kb  = ((lane >> 3) & 1) * 16;
    float nib = g_neg_inv_bw16;

    int mode, bi, bj;
    decode_tile(blockIdx.x, mode, bi, bj);
    const __nv_bfloat16* srcs[4];
    set_srcs(mode, bi, bj, srcs);
    prefetch_chunk(srcs, 0, dbase, tid, (mode == 2) ? 4 : 3);
    CP_COMMIT();

    for (int tile = blockIdx.x;;) {
        if (tid < TDIM) {
            naS[tid] = ((mode == 1) ? g_tt : g_ss)[bi * TDIM + tid];
            if (mode == 2) sRow[tid] = ~0ull;
        } else {
            nbS[tid - TDIM] = ((mode == 0) ? g_ss : g_tt)[bj * TDIM + tid - TDIM];
            if (mode == 2) sCol[tid - TDIM] = ~0ull;
        }

        int ntile = tile + PGRID;
        bool have_next = ntile < NTILE;
        int nmode = 0, nbi = 0, nbj = 0;
        if (have_next) decode_tile(ntile, nmode, nbi, nbj);

        float acc[2][8][4];
        #pragma unroll
        for (int mf = 0; mf < 2; mf++)
            #pragma unroll
            for (int nf = 0; nf < 8; nf++)
                #pragma unroll
                for (int e = 0; e < 4; e++) acc[mf][nf][e] = 0.f;

        for (int c = 0; c < NCH; c++) {
            if (c + 1 < NCH) {
                prefetch_chunk(srcs, c + 1, dbase + ((c + 1) & 1) * STAGEB, tid,
                               (mode == 2) ? 4 : 3);
                CP_COMMIT(); CP_WAIT(1);
            } else if (have_next) {
                const __nv_bfloat16* ns[4];
                set_srcs(nmode, nbi, nbj, ns);
                prefetch_chunk(ns, 0, dbase, tid, (nmode == 2) ? 4 : 3);
                CP_COMMIT(); CP_WAIT(1);
            } else {
                CP_WAIT(0);
            }
            __syncthreads();

            u32 sb = dbase + (c & 1) * STAGEB;
            #pragma unroll
            for (int ks = 0; ks < KC / 16; ks++) {
                u32 ah[2][4], al[2][4];
                #pragma unroll
                for (int mf = 0; mf < 2; mf++) {
                    ldsm4(ah[mf], sb + 0 * OPB + swz64(mrow0 + mf * 16 + a_row, ks * 32 + a_kb));
                    ldsm4(al[mf], sb + 1 * OPB + swz64(mrow0 + mf * 16 + a_row, ks * 32 + a_kb));
                }
                u32 bb[8][2];
                #pragma unroll
                for (int np = 0; np < 4; np++) {
                    u32 r[4];
                    ldsm4(r, sb + 2 * OPB + swz64(ncol0 + np * 16 + b_row, ks * 32 + b_kb));
                    bb[2 * np][0] = r[0]; bb[2 * np][1] = r[1];
                    bb[2 * np + 1][0] = r[2]; bb[2 * np + 1][1] = r[3];
                }
                // long reuse-distance schedule: hh rows 0, hh rows 1, lh rows 0, lh rows 1
                #pragma unroll
                for (int nf = 0; nf < 8; nf++) hmma(acc[0][nf], ah[0], bb[nf]);
                #pragma unroll
                for (int nf = 0; nf < 8; nf++) hmma(acc[1][nf], ah[1], bb[nf]);
                #pragma unroll
                for (int nf = 0; nf < 8; nf++) hmma(acc[0][nf], al[0], bb[nf]);
                #pragma unroll
                for (int nf = 0; nf < 8; nf++) hmma(acc[1][nf], al[1], bb[nf]);
                if (mode == 2) {   // hl term only where argmin needs full precision
                    #pragma unroll
                    for (int np = 0; np < 4; np++) {
                        u32 r[4];
                        ldsm4(r, sb + 3 * OPB + swz64(ncol0 + np * 16 + b_row, ks * 32 + b_kb));
                        bb[2 * np][0] = r[0]; bb[2 * np][1] = r[1];
                        bb[2 * np + 1][0] = r[2]; bb[2 * np + 1][1] = r[3];
                    }
                    #pragma unroll
                    for (int nf = 0; nf < 8; nf++) hmma(acc[0][nf], ah[0], bb[nf]);
                    #pragma unroll
                    for (int nf = 0; nf < 8; nf++) hmma(acc[1][nf], ah[1], bb[nf]);
                }
            }
            __syncthreads();
        }

        // ---- register-direct epilogue ----
        float myna[4];
        #pragma unroll
        for (int q = 0; q < 4; q++)
            myna[q] = naS[mrow0 + (q >> 1) * 16 + (q & 1) * 8 + (lane >> 2)];

        float part = 0.f;
        ull rk[4];
        #pragma unroll
        for (int q = 0; q < 4; q++) rk[q] = ~0ull;

        #pragma unroll
        for (int nf = 0; nf < 8; nf++) {
            float nb0 = nbS[ncol0 + nf * 8 + (lane & 3) * 2 + 0];
            float nb1 = nbS[ncol0 + nf * 8 + (lane & 3) * 2 + 1];
            ull ck0 = ~0ull, ck1 = ~0ull;
            #pragma unroll
            for (int mf = 0; mf < 2; mf++)
                #pragma unroll
                for (int e = 0; e < 4; e++) {
                    int eh = e >> 1, el = e & 1;
                    float d2 = myna[mf * 2 + eh] + (el ? nb1 : nb0) - 2.f * acc[mf][nf][e];
                    float ex = __expf(d2 * nib);
                    float e2 = ex * ex, e4 = e2 * e2, e8 = e4 * e4;
                    part += ex + e2 + e4 + e8 + e8 * e8;
                    if (mode == 2) {
                        float d2c = fmaxf(d2, 0.f);
                        ull key = ((ull)__float_as_uint(d2c)) << 32;
                        int rloc = mrow0 + mf * 16 + eh * 8 + (lane >> 2);
                        int cloc = ncol0 + nf * 8 + (lane & 3) * 2 + el;
                        ull kr = key | (unsigned)(bj * TDIM + cloc);
                        if (kr < rk[mf * 2 + eh]) rk[mf * 2 + eh] = kr;
                        ull kc = key | (unsigned)(bi * TDIM + rloc);
                        if (el) { if (kc < ck1) ck1 = kc; } else { if (kc < ck0) ck0 = kc; }
                    }
                }
            if (mode == 2) {
                #pragma unroll
                for (int o = 4; o <= 16; o <<= 1) {
                    ull w0 = __shfl_xor_sync(0xffffffffu, ck0, o);
                    ull w1 = __shfl_xor_sync(0xffffffffu, ck1, o);
                    if (w0 < ck0) ck0 = w0;
                    if (w1 < ck1) ck1 = w1;
                }
                if (lane < 4) {
                    atomicMin(&sCol[ncol0 + nf * 8 + lane * 2 + 0], ck0);
                    atomicMin(&sCol[ncol0 + nf * 8 + lane * 2 + 1], ck1);
                }
            }
        }

        if (mode == 2) {
            #pragma unroll
            for (int q = 0; q < 4; q++) {
                ull v = rk[q];
                #pragma unroll
                for (int o = 1; o <= 2; o <<= 1) {
                    ull w = __shfl_xor_sync(0xffffffffu, v, o);
                    if (w < v) v = w;
                }
                rk[q] = v;
            }
            if ((lane & 3) == 0) {
                #pragma unroll
                for (int q = 0; q < 4; q++)
                    atomicMin(&sRow[mrow0 + (q >> 1) * 16 + (q & 1) * 8 + (lane >> 2)], rk[q]);
            }
        }

        if (mode != 2 && bi != bj) part *= 2.f;
        for (int o = 16; o; o >>= 1) part += __shfl_down_sync(0xffffffffu, part, o);
        if (lane == 0) atomicAdd(&g_ksum[mode], (double)part);

        if (mode == 2) {
            __syncthreads();
            if (tid < TDIM) atomicMin(&g_min_row[bi * TDIM + tid], sRow[tid]);
            else            atomicMin(&g_min_col[bj * TDIM + tid - TDIM], sCol[tid - TDIM]);
        }
        __syncthreads();   // protect naS/nbS/sRow/sCol re-init of next tile

        if (!have_next) break;
        tile = ntile; mode = nmode; bi = nbi; bj = nbj;
        set_srcs(mode, bi, bj, srcs);
    }
}

// ---------------- distillation + finalize ----------------
__device__ __forceinline__ float distill_row(const float* te, const float* st) {
    float mt = te[0], ms = st[0];
    #pragma unroll
    for (int c = 1; c < NCLS; c++) { mt = fmaxf(mt, te[c]); ms = fmaxf(ms, st[c]); }
    float set = 0.f, ses = 0.f;
    #pragma unroll
    for (int c = 0; c < NCLS; c++) { set += __expf(te[c] - mt); ses += __expf(st[c] - ms); }
    float lses = ms + __logf(ses);
    float inv = 1.f / set;
    float acc = 0.f;
    #pragma unroll
    for (int c = 0; c < NCLS; c++)
        acc += __expf(te[c] - mt) * inv * (lses - st[c]);
    return acc;
}

__global__ void dis_final_kernel(const float* __restrict__ sclf,
                                 const float* __restrict__ tclf,
                                 float* __restrict__ out) {
    int tid = threadIdx.x;
    int i = blockIdx.x * 256 + tid;
    int mi  = (int)(g_min_row[i] & 0xffffffffull);
    int mti = (int)(g_min_col[i] & 0xffffffffull);
    float loss = distill_row(sclf + i * NCLS, tclf + mi * NCLS)
               + distill_row(sclf + mti * NCLS, tclf + i * NCLS);
    for (int o = 16; o; o >>= 1) loss += __shfl_down_sync(0xffffffffu, loss, o);
    __shared__ float ws[8];
    if ((tid & 31) == 0) ws[tid >> 5] = loss;
    __syncthreads();
    if (tid == 0) {
        float t = 0.f;
        #pragma unroll
        for (int k = 0; k < 8; k++) t += ws[k];
        g_dispart[blockIdx.x] = (double)t;
    }
    __threadfence();
    __shared__ u32 rank;
    if (tid == 0) rank = atomicAdd(&g_done_ctr, 1u);
    __syncthreads();
    if (rank == 15 && tid == 0) {
        double dis = 0.0, clf = 0.0;
        #pragma unroll
        for (int k = 0; k < 16; k++) { dis += g_dispart[k]; clf += g_clfpart[k]; }
        out[0] = (float)(clf / (double)NSAMP);
        out[1] = (float)(dis / (double)NSAMP);
        out[2] = (float)((g_ksum[0] + g_ksum[1] - 2.0 * g_ksum[2]) /
                         ((double)NSAMP * (double)NSAMP));
    }
}

// ---------------- launch ----------------
extern "C" void kernel_launch(void* const* d_in, const int* in_sizes, int n_in,
                              void* d_out, int out_size) {
    const float* S    = (const float*)d_in[0];
    const float* T    = (const float*)d_in[1];
    const float* sclf = (const float*)d_in[2];
    const float* tclf = (const float*)d_in[3];
    const int*   lab  = (const int*)d_in[4];
    float* out = (float*)d_out;

    cudaFuncSetAttribute(pair_all, cudaFuncAttributeMaxDynamicSharedMemorySize, SMEM_DYN);

    preprocess<<<(2 * NSAMP) / 32, 256>>>(S, T, lab);
    bw_clf_kernel<<<17, 256>>>(sclf, lab);
    pair_all<<<PGRID, 256, SMEM_DYN>>>();
    dis_final_kernel<<<16, 256>>>(sclf, tclf, out);
}